// round 3
// baseline (speedup 1.0000x reference)
#include <cuda_runtime.h>
#include <cstdint>

// Fused Tucker linear layer, fp32, f32x2 packed FMA core GEMM.
// Grid: 256 CTAs x 256 threads, 16 samples/CTA, 2 CTAs/SM.

#define THREADS 256
#define SPB 16      // samples per block
#define SB  4       // phase-1/3 sample sub-batch

// dynamic smem (floats):
//  zs  : [512][20]  z transposed [k][s] (pad 20)      -> 10240
//  usb : 8192       t1 (ph1) / u[16][512] (ph2->ph3)
//  scr : 8192       x-stage+t2 (ph1) / core tile (ph2) / s1 (ph3)
//  fs  : 768        f0..f5
#define ZS_OFF   0
#define US_OFF   10240
#define SCR_OFF  (10240 + 8192)
#define FS_OFF   (SCR_OFF + 8192)
#define SMEM_FLOATS (FS_OFF + 768)
#define SMEM_BYTES  (SMEM_FLOATS * 4)

__global__ __launch_bounds__(THREADS, 2) void tucker_fused(
    const float* __restrict__ x, const float* __restrict__ core,
    const float* __restrict__ f0, const float* __restrict__ f1,
    const float* __restrict__ f2, const float* __restrict__ f3,
    const float* __restrict__ f4, const float* __restrict__ f5,
    const float* __restrict__ bias, float* __restrict__ y)
{
    extern __shared__ float sm[];
    float* zs  = sm + ZS_OFF;
    float* usb = sm + US_OFF;
    float* scr = sm + SCR_OFF;
    float* fs  = sm + FS_OFF;

    const int tid = threadIdx.x;
    const int s0 = blockIdx.x * SPB;

    if (tid < 128) {
        fs[tid]       = f0[tid];
        fs[128 + tid] = f1[tid];
        fs[256 + tid] = f2[tid];
        fs[384 + tid] = f3[tid];
        fs[512 + tid] = f4[tid];
        fs[640 + tid] = f5[tid];
    }
    __syncthreads();

    // ---------------- PHASE 1: in-side contraction -> zs[k][s] ----------------
    {
        const float* f3s = fs + 384;
        const float* f4s = fs + 512;
        const float* f5s = fs + 640;
        float* t1 = usb;   // [SB][256][8] = 8192
        float* t2 = scr;   // [SB][16][8][8] = 4096 (after x-staging done)

        for (int sb = 0; sb < SPB; sb += SB) {
            // 1a: stage 2 raw samples at a time (coalesced), then
            //     t1[sl][de][nn] = sum_f x[de*16+f] * f5[f][nn]
#pragma unroll
            for (int pair = 0; pair < SB / 2; pair++) {
                // stage: 2 samples = 8192 floats, lane-contiguous float4
                float4* xs4 = (float4*)scr;
#pragma unroll
                for (int i = 0; i < 8; i++) {
                    int g = i * THREADS + tid;           // 0..2047 float4s
                    int sl = g >> 10;
                    const float4* xp = (const float4*)(x + ((size_t)(s0 + sb + pair * 2 + sl) << 12));
                    xs4[g] = xp[g & 1023];
                }
                __syncthreads();
#pragma unroll 2
                for (int it = 0; it < 16; it++) {
                    int idx = it * THREADS + tid;        // 0..4095
                    int nn = idx & 7, de = (idx >> 3) & 255, sl = idx >> 11;
                    const float* xb = scr + sl * 4096 + de * 16;
                    float a0 = 0.f, a1 = 0.f;
#pragma unroll
                    for (int f = 0; f < 16; f += 2) {
                        a0 += xb[f] * f5s[f * 8 + nn];
                        a1 += xb[f + 1] * f5s[(f + 1) * 8 + nn];
                    }
                    t1[((pair * 2 + sl) << 11) + (idx & 2047)] = a0 + a1;
                }
                __syncthreads();
            }
            // 1b: t2[sl][d][m][nn] = sum_e f4[e][m] * t1[sl][d*16+e][nn]
#pragma unroll 4
            for (int it = 0; it < 16; it++) {
                int idx = it * THREADS + tid;            // 0..4095
                int nn = idx & 7, m = (idx >> 3) & 7, d = (idx >> 6) & 15, sl = idx >> 10;
                const float* base = t1 + (((sl << 4) + d) << 7) + nn;
                float a0 = 0.f, a1 = 0.f;
#pragma unroll
                for (int e = 0; e < 16; e += 2) {
                    a0 += f4s[e * 8 + m] * base[e * 8];
                    a1 += f4s[(e + 1) * 8 + m] * base[(e + 1) * 8];
                }
                t2[idx] = a0 + a1;
            }
            __syncthreads();
            // 1c: zs[k][sb+sl] = sum_d f3[d][l] * t2[sl][d][m][nn],  k = l*64+m*8+nn
#pragma unroll 4
            for (int it = 0; it < 8; it++) {
                int idx = it * THREADS + tid;            // 0..2047
                int k = idx & 511, sl = idx >> 9;
                int mn = k & 63, l = k >> 6;
                const float* base = t2 + (sl << 10) + mn;
                float a0 = 0.f, a1 = 0.f;
#pragma unroll
                for (int d = 0; d < 16; d += 2) {
                    a0 += f3s[d * 8 + l] * base[d << 6];
                    a1 += f3s[(d + 1) * 8 + l] * base[(d + 1) << 6];
                }
                zs[k * 20 + sb + sl] = a0 + a1;
            }
            __syncthreads();
        }
    }

    // ---------------- PHASE 2: U[16,512] = Z @ core^T (f32x2 packed FMA) -----
    {
        const int sg = tid >> 7;      // 0/1 -> s block of 8
        const int og = tid & 127;     // o block of 4
        float* tile = scr;            // [512 o][16] swizzled, 8192 floats

        unsigned long long acc2[4][4];   // [si2][oi]; lanes = (s, s+1), s = sg*8+si2*2
#pragma unroll
        for (int a = 0; a < 4; a++)
#pragma unroll
            for (int b = 0; b < 4; b++) acc2[a][b] = 0ull;

        // prefetch k-tile 0 (core row-major [o][k], k-major float4s)
        float4 pf[8];
#pragma unroll
        for (int i = 0; i < 8; i++) {
            int g = i * THREADS + tid;            // 0..2047 = 512 o x 4 kq
            int o = g >> 2, kq = g & 3;
            pf[i] = ((const float4*)core)[o * 128 + kq];
        }

#pragma unroll 1
        for (int kt = 0; kt < 32; kt++) {
            __syncthreads();     // previous chunk's reads complete
#pragma unroll
            for (int i = 0; i < 8; i++) {
                int g = i * THREADS + tid;
                int o = g >> 2, kq = g & 3;
                int slot = kq ^ ((o >> 2) & 3);
                *(float4*)&tile[o * 16 + slot * 4] = pf[i];
            }
            if (kt < 31) {
#pragma unroll
                for (int i = 0; i < 8; i++) {
                    int g = i * THREADS + tid;
                    int o = g >> 2, kq = g & 3;
                    pf[i] = ((const float4*)core)[o * 128 + (kt + 1) * 4 + kq];
                }
            }
            __syncthreads();     // tile visible

#pragma unroll
            for (int kq = 0; kq < 4; kq++) {
                float bb[4][4];
                const int slot = kq ^ (og & 3);
#pragma unroll
                for (int oi = 0; oi < 4; oi++)
                    *(float4*)bb[oi] = *(const float4*)&tile[(og * 4 + oi) * 16 + slot * 4];
                unsigned long long bd[4][4];
#pragma unroll
                for (int oi = 0; oi < 4; oi++)
#pragma unroll
                    for (int k = 0; k < 4; k++)
                        asm("mov.b64 %0, {%1, %1};" : "=l"(bd[oi][k]) : "f"(bb[oi][k]));
#pragma unroll
                for (int k = 0; k < 4; k++) {
                    const float* ap = zs + (kt * 16 + kq * 4 + k) * 20 + sg * 8;
                    ulonglong2 A0 = *(const ulonglong2*)ap;        // s0..s3
                    ulonglong2 A1 = *(const ulonglong2*)(ap + 4);  // s4..s7
                    unsigned long long av[4] = {A0.x, A0.y, A1.x, A1.y};
#pragma unroll
                    for (int oi = 0; oi < 4; oi++)
#pragma unroll
                        for (int si2 = 0; si2 < 4; si2++)
                            asm("fma.rn.f32x2 %0, %1, %2, %0;"
                                : "+l"(acc2[si2][oi]) : "l"(av[si2]), "l"(bd[oi][k]));
                }
            }
        }

        __syncthreads();   // tile reads done before usb (separate region, but order ph3 scr use)
        // unpack + store U to usb[s][512]
#pragma unroll
        for (int si2 = 0; si2 < 4; si2++) {
            float lo[4], hi[4];
#pragma unroll
            for (int oi = 0; oi < 4; oi++)
                asm("mov.b64 {%0, %1}, %2;" : "=f"(lo[oi]), "=f"(hi[oi]) : "l"(acc2[si2][oi]));
            int s = sg * 8 + si2 * 2;
            *(float4*)&usb[s * 512 + og * 4]       = make_float4(lo[0], lo[1], lo[2], lo[3]);
            *(float4*)&usb[(s + 1) * 512 + og * 4] = make_float4(hi[0], hi[1], hi[2], hi[3]);
        }
        __syncthreads();
    }

    // ---------------- PHASE 3: out-side expansion + bias -> y -----------------
    {
        const float* f0s = fs;
        const float* f1s = fs + 128;
        const float* f2s = fs + 256;
        float* s1 = scr;   // [SB][16][8][8] = 4096

        for (int sb = 0; sb < SPB; sb += SB) {
            // s1[sl][a][j][k] = sum_i f0[a][i] * u[s][i*64 + j*8 + k]
#pragma unroll 4
            for (int it = 0; it < 16; it++) {
                int idx = it * THREADS + tid;            // 0..4095
                int jk = idx & 63, a = (idx >> 6) & 15, sl = idx >> 10;
                const float* ub = usb + (sb + sl) * 512 + jk;
                float a0 = 0.f, a1 = 0.f;
#pragma unroll
                for (int i = 0; i < 8; i += 2) {
                    a0 += f0s[a * 8 + i] * ub[i * 64];
                    a1 += f0s[a * 8 + i + 1] * ub[(i + 1) * 64];
                }
                s1[idx] = a0 + a1;
            }
            __syncthreads();
            // y = sum_k f2[c][k] * (sum_j f1[b][j] * s1[sl][a][j][k]) + bias
#pragma unroll
            for (int it = 0; it < 4; it++) {
                int r = it * THREADS + tid;              // 0..1023 = sl*256 + a*16 + b
                int b = r & 15, a = (r >> 4) & 15, sl = r >> 8;
                const float* sp = s1 + ((sl * 16 + a) << 6);
                float w[8];
#pragma unroll
                for (int k = 0; k < 8; k++) {
                    float acc = 0.f;
#pragma unroll
                    for (int j = 0; j < 8; j++) acc += f1s[b * 8 + j] * sp[j * 8 + k];
                    w[k] = acc;
                }
                float* yo = y + ((size_t)(s0 + sb + sl) << 12) + a * 256 + b * 16;
                const float4* bp = (const float4*)(bias + a * 256 + b * 16);
#pragma unroll
                for (int c4 = 0; c4 < 4; c4++) {
                    float4 bv = __ldg(bp + c4);
                    float out[4] = {bv.x, bv.y, bv.z, bv.w};
#pragma unroll
                    for (int ci = 0; ci < 4; ci++) {
                        int c = c4 * 4 + ci;
#pragma unroll
                        for (int k = 0; k < 8; k++) out[ci] += f2s[c * 8 + k] * w[k];
                    }
                    *(float4*)(yo + c4 * 4) = make_float4(out[0], out[1], out[2], out[3]);
                }
            }
            __syncthreads();
        }
    }
}

extern "C" void kernel_launch(void* const* d_in, const int* in_sizes, int n_in,
                              void* d_out, int out_size) {
    const float* x    = (const float*)d_in[0];
    const float* core = (const float*)d_in[1];
    const float* f0   = (const float*)d_in[2];
    const float* f1   = (const float*)d_in[3];
    const float* f2   = (const float*)d_in[4];
    const float* f3   = (const float*)d_in[5];
    const float* f4   = (const float*)d_in[6];
    const float* f5   = (const float*)d_in[7];
    const float* bias = (const float*)d_in[8];
    float* y = (float*)d_out;

    cudaFuncSetAttribute(tucker_fused, cudaFuncAttributeMaxDynamicSharedMemorySize, SMEM_BYTES);
    tucker_fused<<<256, THREADS, SMEM_BYTES>>>(x, core, f0, f1, f2, f3, f4, f5, bias, y);
}